// round 9
// baseline (speedup 1.0000x reference)
#include <cuda_runtime.h>
#include <cuda_fp16.h>
#include <cstdint>

#define B_   16
#define C_   256
#define T_   2048
#define KC_  2048
#define BT_  32768
#define QELEMS 8388608

#define SCALE_X 16.0f
#define SCALE_E 2048.0f
#define INV_SCALE 3.0517578125e-05f   // 2^-15, exact
#define TAU 1.2e-4f                   // ambiguity threshold (~19 sigma of fast-path d2 error)

// ---------- global scratch ----------
__device__ float  g_xt[BT_ * C_];   // exact fp32 transposed x (for exact fixup)
__device__ __half g_Ah[BT_ * C_];   // x hi (scaled by 16)
__device__ __half g_Bh[KC_ * C_];   // cb hi (scaled by 2048)
__device__ float  g_xsq[BT_];
__device__ float  g_esq[KC_];
__device__ unsigned long long g_part[BT_ * 32];   // (best,sec) x 16 tiles
__device__ int    g_idx[BT_];
__device__ int    g_namb;
__device__ int    g_alist[BT_];
__device__ unsigned long long g_fix[BT_];
__device__ double g_mse;

__device__ __forceinline__ uint32_t smem_u32(const void* p) {
  uint32_t a;
  asm("{ .reg .u64 t; cvta.to.shared.u64 t, %1; cvt.u32.u64 %0, t; }" : "=r"(a) : "l"(p));
  return a;
}
__device__ __forceinline__ void cpa16(uint32_t dst, const void* src) {
  asm volatile("cp.async.cg.shared.global [%0], [%1], 16;" :: "r"(dst), "l"(src));
}
__device__ __forceinline__ void mma_f16(float* c, const uint32_t* a, const uint32_t* b) {
  asm volatile(
      "mma.sync.aligned.m16n8k16.row.col.f32.f16.f16.f32 "
      "{%0,%1,%2,%3},{%4,%5,%6,%7},{%8,%9},{%0,%1,%2,%3};"
      : "+f"(c[0]), "+f"(c[1]), "+f"(c[2]), "+f"(c[3])
      : "r"(a[0]), "r"(a[1]), "r"(a[2]), "r"(a[3]), "r"(b[0]), "r"(b[1]));
}
__device__ __forceinline__ void merge2(unsigned long long& b, unsigned long long& s,
                                       unsigned long long ob, unsigned long long os) {
  if (ob < b) { s = (b < os) ? b : os; b = ob; }
  else        { s = (ob < s) ? ob : s; }
}

__global__ void k_init() { g_mse = 0.0; g_namb = 0; }

// ---- fused transpose + exact-x store + fp16 hi + x_sq (R1 bit-order) ----
__global__ __launch_bounds__(256) void k_prep_x(const float* __restrict__ x) {
  __shared__ float sm[256][33];
  int b = blockIdx.x >> 6;
  int t0 = (blockIdx.x & 63) << 5;
  int tid = threadIdx.x, lane = tid & 31, w = tid >> 5;
#pragma unroll
  for (int i = 0; i < 32; ++i) {
    int c = i * 8 + w;
    sm[c][lane] = x[((size_t)(b * C_ + c)) * T_ + t0 + lane];
  }
  __syncthreads();
#pragma unroll
  for (int q = 0; q < 4; ++q) {
    int rl = w * 4 + q;
    int m = b * T_ + t0 + rl;
    float s = 0.f;
#pragma unroll
    for (int kc = 0; kc < 8; ++kc) {
      float v = sm[kc * 32 + lane][rl];
      s = __fmaf_rn(v, v, s);                 // bit-identical to R1 order
      g_xt[(size_t)m * C_ + kc * 32 + lane] = v;
      g_Ah[(size_t)m * C_ + kc * 32 + lane] = __float2half_rn(v * SCALE_X);
    }
#pragma unroll
    for (int o = 16; o > 0; o >>= 1) s += __shfl_xor_sync(0xffffffffu, s, o);
    if (lane == 0) g_xsq[m] = s;
  }
}

__global__ __launch_bounds__(256) void k_prep_cb(const float* __restrict__ cb) {
  int n = blockIdx.x, c = threadIdx.x;
  g_Bh[(size_t)n * C_ + c] = __float2half_rn(cb[(size_t)n * C_ + c] * SCALE_E);
}

__global__ void k_esq(const float* __restrict__ cb) {   // identical to R1
  int row = blockIdx.x * 8 + (threadIdx.x >> 5);
  int lane = threadIdx.x & 31;
  const float* p = cb + (size_t)row * C_;
  float s = 0.f;
#pragma unroll
  for (int i = 0; i < C_; i += 32) { float v = p[i + lane]; s = __fmaf_rn(v, v, s); }
#pragma unroll
  for (int o = 16; o > 0; o >>= 1) s += __shfl_xor_sync(0xffffffffu, s, o);
  if (lane == 0) g_esq[row] = s;
}

// ---- main: fp16 mma.sync, 512 threads, warp tile 32x32 (acc=32 regs),
// all 8 k-chunks prefetched into 8 smem stages (160KB, 1 CTA/SM) ----
#define ROWB 80          // 32 halves data + 8 pad
#define STAGE 20480
#define OFF_B 10240
#define SMEM_MAIN 163840

__global__ __launch_bounds__(512) void k_main() {
  extern __shared__ __align__(16) char smem[];
  uint32_t sb = smem_u32(smem);
  const int tid = threadIdx.x, lane = tid & 31, wid = tid >> 5;
  const int mt = blockIdx.x >> 4, nt = blockIdx.x & 15;
  const int m0 = mt << 7, n0 = nt << 7;
  const int wm = wid & 3, wn = wid >> 2;          // warp grid 4(M) x 4(N)
  const int g = lane >> 2, tig = lane & 3;

  float acc[2][4][4];
#pragma unroll
  for (int i = 0; i < 2; ++i)
#pragma unroll
    for (int j = 0; j < 4; ++j)
#pragma unroll
      for (int k = 0; k < 4; ++k) acc[i][j][k] = 0.f;

  // prefetch ALL 8 k-chunks (one commit group each)
  const int r0 = tid >> 2, c0 = tid & 3;   // 128 rows x 4 x 16B = full stage half
#pragma unroll
  for (int s = 0; s < 8; ++s) {
    int k0 = s * 32;
    uint32_t d = sb + s * STAGE;
    cpa16(d + r0 * ROWB + c0 * 16,         g_Ah + (size_t)(m0 + r0) * C_ + k0 + c0 * 8);
    cpa16(d + OFF_B + r0 * ROWB + c0 * 16, g_Bh + (size_t)(n0 + r0) * C_ + k0 + c0 * 8);
    asm volatile("cp.async.commit_group;" ::: "memory");
  }

#pragma unroll
  for (int s = 0; s < 8; ++s) {
    switch (s) {   // wait until chunks 0..s have landed
      case 0: asm volatile("cp.async.wait_group 7;" ::: "memory"); break;
      case 1: asm volatile("cp.async.wait_group 6;" ::: "memory"); break;
      case 2: asm volatile("cp.async.wait_group 5;" ::: "memory"); break;
      case 3: asm volatile("cp.async.wait_group 4;" ::: "memory"); break;
      case 4: asm volatile("cp.async.wait_group 3;" ::: "memory"); break;
      case 5: asm volatile("cp.async.wait_group 2;" ::: "memory"); break;
      case 6: asm volatile("cp.async.wait_group 1;" ::: "memory"); break;
      default: asm volatile("cp.async.wait_group 0;" ::: "memory"); break;
    }
    __syncthreads();

    const char* buf = smem + s * STAGE;
#pragma unroll
    for (int kk = 0; kk < 32; kk += 16) {
      const int ak = kk + 2 * tig;
      uint32_t AH[2][4], BH[4][2];
#pragma unroll
      for (int mf = 0; mf < 2; ++mf) {
        int ra = wm * 32 + mf * 16 + g;
        AH[mf][0] = *(const uint32_t*)(buf + ra * ROWB + ak * 2);
        AH[mf][1] = *(const uint32_t*)(buf + (ra + 8) * ROWB + ak * 2);
        AH[mf][2] = *(const uint32_t*)(buf + ra * ROWB + (ak + 8) * 2);
        AH[mf][3] = *(const uint32_t*)(buf + (ra + 8) * ROWB + (ak + 8) * 2);
      }
#pragma unroll
      for (int nf = 0; nf < 4; ++nf) {
        int rb = wn * 32 + nf * 8 + g;
        BH[nf][0] = *(const uint32_t*)(buf + OFF_B + rb * ROWB + ak * 2);
        BH[nf][1] = *(const uint32_t*)(buf + OFF_B + rb * ROWB + (ak + 8) * 2);
      }
#pragma unroll
      for (int mf = 0; mf < 2; ++mf)
#pragma unroll
        for (int nf = 0; nf < 4; ++nf) mma_f16(acc[mf][nf], AH[mf], BH[nf]);
    }
    // no trailing sync needed: each stage is written once, never reused
  }

  // ---- epilogue: d2 + (best, second) argmin ----
  unsigned long long* sred = (unsigned long long*)smem;   // stage-0 area, all reads done
#pragma unroll
  for (int mf = 0; mf < 2; ++mf)
#pragma unroll
    for (int h = 0; h < 2; ++h) {
      int rl = wm * 32 + mf * 16 + g + 8 * h;
      float xs = g_xsq[m0 + rl];
      unsigned long long best = ~0ull, sec = ~0ull;
#pragma unroll
      for (int nf = 0; nf < 4; ++nf)
#pragma unroll
        for (int e = 0; e < 2; ++e) {
          int n = n0 + wn * 32 + nf * 8 + 2 * tig + e;
          float dot = __fmul_rn(acc[mf][nf][2 * h + e], INV_SCALE);
          float d2 = __fadd_rn(__fmaf_rn(-2.0f, dot, xs), g_esq[n]);
          unsigned long long p =
              (((unsigned long long)__float_as_uint(d2)) << 32) | (unsigned)n;
          if (p < best) { sec = best; best = p; }
          else if (p < sec) sec = p;
        }
      unsigned long long ob = __shfl_xor_sync(0xffffffffu, best, 1);
      unsigned long long os = __shfl_xor_sync(0xffffffffu, sec, 1);
      merge2(best, sec, ob, os);
      ob = __shfl_xor_sync(0xffffffffu, best, 2);
      os = __shfl_xor_sync(0xffffffffu, sec, 2);
      merge2(best, sec, ob, os);
      if (tig == 0) { sred[rl * 8 + wn * 2] = best; sred[rl * 8 + wn * 2 + 1] = sec; }
    }
  __syncthreads();
  if (tid < 128) {
    unsigned long long b = sred[tid * 8], s = sred[tid * 8 + 1];
#pragma unroll
    for (int k = 1; k < 4; ++k) merge2(b, s, sred[tid * 8 + 2 * k], sred[tid * 8 + 2 * k + 1]);
    g_part[(size_t)(m0 + tid) * 32 + nt * 2] = b;
    g_part[(size_t)(m0 + tid) * 32 + nt * 2 + 1] = s;
  }
}

// ---- reduce 16 (best,sec) pairs; flag ambiguous rows ----
__global__ void k_reduce(float* __restrict__ out_idxf) {
  int r = blockIdx.x * 256 + threadIdx.x;
  unsigned long long b = g_part[(size_t)r * 32], s = g_part[(size_t)r * 32 + 1];
#pragma unroll
  for (int k = 1; k < 16; ++k)
    merge2(b, s, g_part[(size_t)r * 32 + 2 * k], g_part[(size_t)r * 32 + 2 * k + 1]);
  int idx = (int)(b & 0xffffffffu);
  g_idx[r] = idx;
  out_idxf[r] = (float)idx;
  float fb = __uint_as_float((uint32_t)(b >> 32));
  float fs = __uint_as_float((uint32_t)(s >> 32));
  if (__fsub_rn(fs, fb) < TAU) {
    g_fix[r] = ~0ull;
    int slot = atomicAdd(&g_namb, 1);
    g_alist[slot] = r;
  }
}

// ---- exact fixup: recompute all 2048 d2 bit-identically to R1 for flagged rows ----
__global__ __launch_bounds__(256) void k_fixup(const float* __restrict__ cb) {
  __shared__ float xr[8][257];
  __shared__ float sxs[8];
  __shared__ int srow[8];
  int tid = threadIdx.x;
  int cnt = g_namb;
  for (int id = blockIdx.x; (id >> 2) * 8 < cnt; id += gridDim.x) {
    int grp = id >> 2, q = id & 3;
    int base = grp * 8;
    int nrows = cnt - base; if (nrows > 8) nrows = 8;
    __syncthreads();
    if (tid < 8) {
      int rr = (tid < nrows) ? g_alist[base + tid] : g_alist[base];
      srow[tid] = rr;
      sxs[tid] = g_xsq[rr];
    }
    __syncthreads();
    for (int i = tid; i < 8 * 256; i += 256)
      xr[i >> 8][i & 255] = g_xt[(size_t)srow[i >> 8] * C_ + (i & 255)];
    __syncthreads();
#pragma unroll 1
    for (int cj = 0; cj < 2; ++cj) {
      int n = q * 512 + cj * 256 + tid;
      const float* e = cb + (size_t)n * C_;
      float dot[8];
#pragma unroll
      for (int rr = 0; rr < 8; ++rr) dot[rr] = 0.f;
      for (int k = 0; k < 256; ++k) {
        float ev = __ldg(e + k);
#pragma unroll
        for (int rr = 0; rr < 8; ++rr)
          dot[rr] = __fmaf_rn(xr[rr][k], ev, dot[rr]);   // ascending-k chain == R1
      }
      float es = g_esq[n];
#pragma unroll
      for (int rr = 0; rr < 8; ++rr) {
        if (rr < nrows) {
          float d2 = __fadd_rn(__fmaf_rn(-2.0f, dot[rr], sxs[rr]), es);
          unsigned long long p =
              (((unsigned long long)__float_as_uint(d2)) << 32) | (unsigned)n;
          atomicMin(&g_fix[srow[rr]], p);
        }
      }
    }
  }
}

__global__ void k_fixup_b(float* __restrict__ out_idxf) {
  int cnt = g_namb;
  for (int i = blockIdx.x * 256 + threadIdx.x; i < cnt; i += gridDim.x * 256) {
    int row = g_alist[i];
    unsigned long long m = g_fix[row];
    int idx = (int)(m & 0xffffffffu);
    g_idx[row] = idx;
    out_idxf[row] = (float)idx;
  }
}

// ---- gather + MSE ----
__global__ void k_gather(const float* __restrict__ x, const float* __restrict__ cb,
                         float* __restrict__ out) {
  int i = blockIdx.x * 256 + threadIdx.x;
  int t = i & (T_ - 1);
  int bc = i >> 11;
  int c = bc & (C_ - 1);
  int b = bc >> 8;
  int id = g_idx[(b << 11) + t];
  float q = cb[(size_t)id * C_ + c];
  float xv = x[i];
  float diff = __fsub_rn(q, xv);
  out[i] = __fadd_rn(xv, diff);
  float sqf = __fmul_rn(diff, diff);
  double s = (double)sqf;
#pragma unroll
  for (int o = 16; o > 0; o >>= 1) s += __shfl_xor_sync(0xffffffffu, s, o);
  __shared__ double ws[8];
  int lane = threadIdx.x & 31, w = threadIdx.x >> 5;
  if (lane == 0) ws[w] = s;
  __syncthreads();
  if (threadIdx.x == 0) {
    double tot = 0.0;
#pragma unroll
    for (int k = 0; k < 8; ++k) tot += ws[k];
    atomicAdd(&g_mse, tot);
  }
}

__global__ void k_finalize(float* __restrict__ out) {
  float m = (float)(g_mse * (1.0 / (double)QELEMS));
  out[QELEMS] = m;
  out[QELEMS + 1] = 0.25f * m;
}

extern "C" void kernel_launch(void* const* d_in, const int* in_sizes, int n_in,
                              void* d_out, int out_size) {
  const float* x  = (const float*)d_in[0];
  const float* cb = (const float*)d_in[1];
  float* out = (float*)d_out;

  cudaFuncSetAttribute(k_main, cudaFuncAttributeMaxDynamicSharedMemorySize, SMEM_MAIN);

  k_init<<<1, 1>>>();
  k_prep_x<<<B_ * (T_ / 32), 256>>>(x);
  k_prep_cb<<<KC_, 256>>>(cb);
  k_esq<<<KC_ / 8, 256>>>(cb);
  k_main<<<4096, 512, SMEM_MAIN>>>();
  k_reduce<<<BT_ / 256, 256>>>(out + QELEMS + 2);
  k_fixup<<<2048, 256>>>(cb);
  k_fixup_b<<<32, 256>>>(out + QELEMS + 2);
  k_gather<<<QELEMS / 256, 256>>>(x, cb, out);
  k_finalize<<<1, 1>>>(out);
}

// round 11
// speedup vs baseline: 1.0827x; 1.0827x over previous
#include <cuda_runtime.h>
#include <cuda_fp16.h>
#include <cstdint>

#define B_   16
#define C_   256
#define T_   2048
#define KC_  2048
#define BT_  32768
#define QELEMS 8388608

#define SCALE_X 16.0f
#define SCALE_E 2048.0f
#define INV_SCALE 3.0517578125e-05f   // 2^-15, exact
#define TAU 1.2e-4f                   // ambiguity threshold (~19 sigma of fast-path d2 error)

// ---------- global scratch ----------
__device__ float  g_xt[BT_ * C_];   // exact fp32 transposed x (for exact fixup)
__device__ __half g_Ah[BT_ * C_];   // x hi (scaled by 16)
__device__ __half g_Bh[KC_ * C_];   // cb hi (scaled by 2048)
__device__ float  g_xsq[BT_];
__device__ float  g_esq[KC_];
__device__ unsigned long long g_part[BT_ * 32];   // (best,sec) x 16 tiles
__device__ int    g_idx[BT_];
__device__ int    g_namb;
__device__ int    g_alist[BT_];
__device__ unsigned long long g_fix[BT_];
__device__ double g_mse;

__device__ __forceinline__ uint32_t smem_u32(const void* p) {
  uint32_t a;
  asm("{ .reg .u64 t; cvta.to.shared.u64 t, %1; cvt.u32.u64 %0, t; }" : "=r"(a) : "l"(p));
  return a;
}
__device__ __forceinline__ void cpa16(uint32_t dst, const void* src) {
  asm volatile("cp.async.cg.shared.global [%0], [%1], 16;" :: "r"(dst), "l"(src));
}
__device__ __forceinline__ void mma_f16(float* c, const uint32_t* a, const uint32_t* b) {
  asm volatile(
      "mma.sync.aligned.m16n8k16.row.col.f32.f16.f16.f32 "
      "{%0,%1,%2,%3},{%4,%5,%6,%7},{%8,%9},{%0,%1,%2,%3};"
      : "+f"(c[0]), "+f"(c[1]), "+f"(c[2]), "+f"(c[3])
      : "r"(a[0]), "r"(a[1]), "r"(a[2]), "r"(a[3]), "r"(b[0]), "r"(b[1]));
}
__device__ __forceinline__ void merge2(unsigned long long& b, unsigned long long& s,
                                       unsigned long long ob, unsigned long long os) {
  if (ob < b) { s = (b < os) ? b : os; b = ob; }
  else        { s = (ob < s) ? ob : s; }
}

// slot 3: init (kept separate so k_main lands in launch slot 4 for ncu capture)
__global__ void k_init() { g_mse = 0.0; g_namb = 0; }

// ---- slot 1: fused transpose + exact-x store + fp16 hi + x_sq (R1 bit-order) ----
__global__ __launch_bounds__(256) void k_prep_x(const float* __restrict__ x) {
  __shared__ float sm[256][33];
  int b = blockIdx.x >> 6;
  int t0 = (blockIdx.x & 63) << 5;
  int tid = threadIdx.x, lane = tid & 31, w = tid >> 5;
#pragma unroll
  for (int i = 0; i < 32; ++i) {
    int c = i * 8 + w;
    sm[c][lane] = x[((size_t)(b * C_ + c)) * T_ + t0 + lane];
  }
  __syncthreads();
#pragma unroll
  for (int q = 0; q < 4; ++q) {
    int rl = w * 4 + q;
    int m = b * T_ + t0 + rl;
    float s = 0.f;
#pragma unroll
    for (int kc = 0; kc < 8; ++kc) {
      float v = sm[kc * 32 + lane][rl];
      s = __fmaf_rn(v, v, s);                 // bit-identical to R1 order
      g_xt[(size_t)m * C_ + kc * 32 + lane] = v;
      g_Ah[(size_t)m * C_ + kc * 32 + lane] = __float2half_rn(v * SCALE_X);
    }
#pragma unroll
    for (int o = 16; o > 0; o >>= 1) s += __shfl_xor_sync(0xffffffffu, s, o);
    if (lane == 0) g_xsq[m] = s;
  }
}

// ---- slot 2: codebook fp16 split + e_sq (esq chain bit-identical to R1) ----
__global__ __launch_bounds__(256) void k_prep_cbe(const float* __restrict__ cb) {
  int n = blockIdx.x, tid = threadIdx.x;
  g_Bh[(size_t)n * C_ + tid] = __float2half_rn(cb[(size_t)n * C_ + tid] * SCALE_E);
  if (tid < 32) {
    const float* p = cb + (size_t)n * C_;
    float s = 0.f;
#pragma unroll
    for (int i = 0; i < C_; i += 32) { float v = p[i + tid]; s = __fmaf_rn(v, v, s); }
#pragma unroll
    for (int o = 16; o > 0; o >>= 1) s += __shfl_xor_sync(0xffffffffu, s, o);
    if (tid == 0) g_esq[n] = s;
  }
}

// ---- slot 4: fp16 mma.sync GEMM + best/second argmin epilogue ----
// CTA 128x128, BK=32, 4-stage ring with depth-3 overlap, 2 CTAs/SM.
#define ROWB 80          // 32 halves data + 8 pad
#define STAGE 20480
#define OFF_B 10240
#define SMEM_MAIN 81920

__global__ __launch_bounds__(256, 2) void k_main() {
  extern __shared__ __align__(16) char smem[];
  uint32_t sb = smem_u32(smem);
  const int tid = threadIdx.x, lane = tid & 31, wid = tid >> 5;
  const int mt = blockIdx.x >> 4, nt = blockIdx.x & 15;
  const int m0 = mt << 7, n0 = nt << 7;
  const int wm = wid & 1, wn = wid >> 1;          // warp grid 2(M) x 4(N)
  const int g = lane >> 2, tig = lane & 3;

  float acc[4][4][4];
#pragma unroll
  for (int i = 0; i < 4; ++i)
#pragma unroll
    for (int j = 0; j < 4; ++j)
#pragma unroll
      for (int k = 0; k < 4; ++k) acc[i][j][k] = 0.f;

  const int r0 = tid >> 2, c0 = tid & 3;   // 64 rows per pass, 4x16B per row

  auto issue = [&](int s) {
    int k0 = s * 32;
    uint32_t d = sb + (s & 3) * STAGE;
    cpa16(d + r0 * ROWB + c0 * 16,          g_Ah + (size_t)(m0 + r0) * C_ + k0 + c0 * 8);
    cpa16(d + (r0 + 64) * ROWB + c0 * 16,   g_Ah + (size_t)(m0 + r0 + 64) * C_ + k0 + c0 * 8);
    cpa16(d + OFF_B + r0 * ROWB + c0 * 16,        g_Bh + (size_t)(n0 + r0) * C_ + k0 + c0 * 8);
    cpa16(d + OFF_B + (r0 + 64) * ROWB + c0 * 16, g_Bh + (size_t)(n0 + r0 + 64) * C_ + k0 + c0 * 8);
    asm volatile("cp.async.commit_group;" ::: "memory");
  };

  issue(0); issue(1); issue(2);

#pragma unroll 1
  for (int s = 0; s < 8; ++s) {
    if (s < 6)      asm volatile("cp.async.wait_group 2;" ::: "memory");
    else if (s == 6) asm volatile("cp.async.wait_group 1;" ::: "memory");
    else             asm volatile("cp.async.wait_group 0;" ::: "memory");
    __syncthreads();                 // all threads done with stage (s&3)'s previous life
    if (s + 3 < 8) issue(s + 3);     // safe: after barrier, WAR on ring slot closed

    const char* buf = smem + (s & 3) * STAGE;
#pragma unroll
    for (int kk = 0; kk < 32; kk += 16) {
      const int ak = kk + 2 * tig;
      uint32_t AH[4][4], BH[4][2];
#pragma unroll
      for (int mf = 0; mf < 4; ++mf) {
        int ra = wm * 64 + mf * 16 + g;
        AH[mf][0] = *(const uint32_t*)(buf + ra * ROWB + ak * 2);
        AH[mf][1] = *(const uint32_t*)(buf + (ra + 8) * ROWB + ak * 2);
        AH[mf][2] = *(const uint32_t*)(buf + ra * ROWB + (ak + 8) * 2);
        AH[mf][3] = *(const uint32_t*)(buf + (ra + 8) * ROWB + (ak + 8) * 2);
      }
#pragma unroll
      for (int nf = 0; nf < 4; ++nf) {
        int rb = wn * 32 + nf * 8 + g;
        BH[nf][0] = *(const uint32_t*)(buf + OFF_B + rb * ROWB + ak * 2);
        BH[nf][1] = *(const uint32_t*)(buf + OFF_B + rb * ROWB + (ak + 8) * 2);
      }
#pragma unroll
      for (int mf = 0; mf < 4; ++mf)
#pragma unroll
        for (int nf = 0; nf < 4; ++nf) mma_f16(acc[mf][nf], AH[mf], BH[nf]);
    }
  }

  // ---- epilogue: d2 + (best, second) argmin ----
  unsigned long long* sred = (unsigned long long*)smem;   // stage-0 region (retired)
#pragma unroll
  for (int mf = 0; mf < 4; ++mf)
#pragma unroll
    for (int h = 0; h < 2; ++h) {
      int rl = wm * 64 + mf * 16 + g + 8 * h;
      float xs = g_xsq[m0 + rl];
      unsigned long long best = ~0ull, sec = ~0ull;
#pragma unroll
      for (int nf = 0; nf < 4; ++nf)
#pragma unroll
        for (int e = 0; e < 2; ++e) {
          int n = n0 + wn * 32 + nf * 8 + 2 * tig + e;
          float dot = __fmul_rn(acc[mf][nf][2 * h + e], INV_SCALE);
          float d2 = __fadd_rn(__fmaf_rn(-2.0f, dot, xs), g_esq[n]);
          unsigned long long p =
              (((unsigned long long)__float_as_uint(d2)) << 32) | (unsigned)n;
          if (p < best) { sec = best; best = p; }
          else if (p < sec) sec = p;
        }
      unsigned long long ob = __shfl_xor_sync(0xffffffffu, best, 1);
      unsigned long long os = __shfl_xor_sync(0xffffffffu, sec, 1);
      merge2(best, sec, ob, os);
      ob = __shfl_xor_sync(0xffffffffu, best, 2);
      os = __shfl_xor_sync(0xffffffffu, sec, 2);
      merge2(best, sec, ob, os);
      if (tig == 0) { sred[rl * 8 + wn * 2] = best; sred[rl * 8 + wn * 2 + 1] = sec; }
    }
  __syncthreads();
  if (tid < 128) {
    unsigned long long b = sred[tid * 8], s = sred[tid * 8 + 1];
#pragma unroll
    for (int k = 1; k < 4; ++k) merge2(b, s, sred[tid * 8 + 2 * k], sred[tid * 8 + 2 * k + 1]);
    g_part[(size_t)(m0 + tid) * 32 + nt * 2] = b;
    g_part[(size_t)(m0 + tid) * 32 + nt * 2 + 1] = s;
  }
}

// ---- slot 5: reduce 16 (best,sec) pairs; flag ambiguous rows ----
__global__ void k_reduce(float* __restrict__ out_idxf) {
  int r = blockIdx.x * 256 + threadIdx.x;
  unsigned long long b = g_part[(size_t)r * 32], s = g_part[(size_t)r * 32 + 1];
#pragma unroll
  for (int k = 1; k < 16; ++k)
    merge2(b, s, g_part[(size_t)r * 32 + 2 * k], g_part[(size_t)r * 32 + 2 * k + 1]);
  int idx = (int)(b & 0xffffffffu);
  g_idx[r] = idx;
  out_idxf[r] = (float)idx;
  float fb = __uint_as_float((uint32_t)(b >> 32));
  float fs = __uint_as_float((uint32_t)(s >> 32));
  if (__fsub_rn(fs, fb) < TAU) {
    g_fix[r] = ~0ull;
    int slot = atomicAdd(&g_namb, 1);
    g_alist[slot] = r;
  }
}

// ---- slot 6: exact fixup (bit-identical to R1 for flagged rows) ----
__global__ __launch_bounds__(256) void k_fixup(const float* __restrict__ cb) {
  __shared__ float xr[8][257];
  __shared__ float sxs[8];
  __shared__ int srow[8];
  int tid = threadIdx.x;
  int cnt = g_namb;
  for (int id = blockIdx.x; (id >> 2) * 8 < cnt; id += gridDim.x) {
    int grp = id >> 2, q = id & 3;
    int base = grp * 8;
    int nrows = cnt - base; if (nrows > 8) nrows = 8;
    __syncthreads();
    if (tid < 8) {
      int rr = (tid < nrows) ? g_alist[base + tid] : g_alist[base];
      srow[tid] = rr;
      sxs[tid] = g_xsq[rr];
    }
    __syncthreads();
    for (int i = tid; i < 8 * 256; i += 256)
      xr[i >> 8][i & 255] = g_xt[(size_t)srow[i >> 8] * C_ + (i & 255)];
    __syncthreads();
#pragma unroll 1
    for (int cj = 0; cj < 2; ++cj) {
      int n = q * 512 + cj * 256 + tid;
      const float* e = cb + (size_t)n * C_;
      float dot[8];
#pragma unroll
      for (int rr = 0; rr < 8; ++rr) dot[rr] = 0.f;
      for (int k = 0; k < 256; ++k) {
        float ev = __ldg(e + k);
#pragma unroll
        for (int rr = 0; rr < 8; ++rr)
          dot[rr] = __fmaf_rn(xr[rr][k], ev, dot[rr]);   // ascending-k chain == R1
      }
      float es = g_esq[n];
#pragma unroll
      for (int rr = 0; rr < 8; ++rr) {
        if (rr < nrows) {
          float d2 = __fadd_rn(__fmaf_rn(-2.0f, dot[rr], sxs[rr]), es);
          unsigned long long p =
              (((unsigned long long)__float_as_uint(d2)) << 32) | (unsigned)n;
          atomicMin(&g_fix[srow[rr]], p);
        }
      }
    }
  }
}

__global__ void k_fixup_b(float* __restrict__ out_idxf) {
  int cnt = g_namb;
  for (int i = blockIdx.x * 256 + threadIdx.x; i < cnt; i += gridDim.x * 256) {
    int row = g_alist[i];
    unsigned long long m = g_fix[row];
    int idx = (int)(m & 0xffffffffu);
    g_idx[row] = idx;
    out_idxf[row] = (float)idx;
  }
}

// ---- gather + MSE ----
__global__ void k_gather(const float* __restrict__ x, const float* __restrict__ cb,
                         float* __restrict__ out) {
  int i = blockIdx.x * 256 + threadIdx.x;
  int t = i & (T_ - 1);
  int bc = i >> 11;
  int c = bc & (C_ - 1);
  int b = bc >> 8;
  int id = g_idx[(b << 11) + t];
  float q = cb[(size_t)id * C_ + c];
  float xv = x[i];
  float diff = __fsub_rn(q, xv);
  out[i] = __fadd_rn(xv, diff);
  float sqf = __fmul_rn(diff, diff);
  double s = (double)sqf;
#pragma unroll
  for (int o = 16; o > 0; o >>= 1) s += __shfl_xor_sync(0xffffffffu, s, o);
  __shared__ double ws[8];
  int lane = threadIdx.x & 31, w = threadIdx.x >> 5;
  if (lane == 0) ws[w] = s;
  __syncthreads();
  if (threadIdx.x == 0) {
    double tot = 0.0;
#pragma unroll
    for (int k = 0; k < 8; ++k) tot += ws[k];
    atomicAdd(&g_mse, tot);
  }
}

__global__ void k_finalize(float* __restrict__ out) {
  float m = (float)(g_mse * (1.0 / (double)QELEMS));
  out[QELEMS] = m;
  out[QELEMS + 1] = 0.25f * m;
}

extern "C" void kernel_launch(void* const* d_in, const int* in_sizes, int n_in,
                              void* d_out, int out_size) {
  const float* x  = (const float*)d_in[0];
  const float* cb = (const float*)d_in[1];
  float* out = (float*)d_out;

  cudaFuncSetAttribute(k_main, cudaFuncAttributeMaxDynamicSharedMemorySize, SMEM_MAIN);

  k_prep_x<<<B_ * (T_ / 32), 256>>>(x);          // launch 1
  k_prep_cbe<<<KC_, 256>>>(cb);                  // launch 2
  k_init<<<1, 1>>>();                            // launch 3
  k_main<<<4096, 256, SMEM_MAIN>>>();            // launch 4  <- ncu capture slot
  k_reduce<<<BT_ / 256, 256>>>(out + QELEMS + 2);// launch 5
  k_fixup<<<2048, 256>>>(cb);                    // launch 6
  k_fixup_b<<<32, 256>>>(out + QELEMS + 2);      // launch 7
  k_gather<<<QELEMS / 256, 256>>>(x, cb, out);   // launch 8
  k_finalize<<<1, 1>>>(out);                     // launch 9
}